// round 6
// baseline (speedup 1.0000x reference)
#include <cuda_runtime.h>
#include <math.h>

// ---------------- problem constants ----------------
constexpr int NN    = 50000;         // nodes
constexpr int EE    = 500000;        // raw edges
constexpr int ETOT  = EE + NN;       // + self loops
constexpr int FIN   = 128;
constexpr int HID   = 32;
constexpr int HEADS = 8;
constexpr int C1    = HEADS * HID;   // 256
constexpr int OUTC  = 64;
constexpr float NEG = 0.2f;

constexpr unsigned FULL = 0xffffffffu;
constexpr int CHUNKS = 4;            // register-cached edge chunks (deg <= 128 fast path)

// ---------------- device scratch ----------------
__device__ float g_h1p[NN * C1];    // layer1 projection  x@W1
__device__ float g_h1 [NN * C1];    // layer1 output (elu(agg+b1))
__device__ float g_h2p[NN * OUTC];  // layer2 projection  h1@W2
__device__ float g_al1[NN * HEADS];
__device__ float g_ar1[NN * HEADS];
__device__ float g_al2[NN];
__device__ float g_ar2[NN];

__device__ int g_rowptr[NN + 1];
__device__ int g_cnt[NN];
__device__ int g_cursor[NN];
__device__ int g_srcs[ETOT];        // src node per CSR slot (sorted by dst)

constexpr int SCAN_B = 1024;
constexpr int NBLK = (NN + SCAN_B - 1) / SCAN_B;   // 49
__device__ int g_bsum[NBLK];
__device__ int g_boff[NBLK];

// ---------------- helpers ----------------
__device__ __forceinline__ void edge_sd(const int* __restrict__ ei, int e, int& s, int& d) {
    if (e < EE) { s = ei[e]; d = ei[EE + e]; }
    else        { s = d = e - EE; }
}

__device__ __forceinline__ float warp_max(float v) {
    #pragma unroll
    for (int o = 16; o; o >>= 1) v = fmaxf(v, __shfl_xor_sync(FULL, v, o));
    return v;
}
__device__ __forceinline__ float warp_sum(float v) {
    #pragma unroll
    for (int o = 16; o; o >>= 1) v += __shfl_xor_sync(FULL, v, o);
    return v;
}
// merge (m, d) online-softmax states across the warp
__device__ __forceinline__ void warp_softmax_merge(float& m, float& d) {
    #pragma unroll
    for (int o = 16; o; o >>= 1) {
        float m2 = __shfl_xor_sync(FULL, m, o);
        float d2 = __shfl_xor_sync(FULL, d, o);
        float M = fmaxf(m, m2);
        d = d * __expf(m - M) + d2 * __expf(m2 - M);
        m = M;
    }
}
__device__ __forceinline__ float lrelu(float v) { return v > 0.f ? v : NEG * v; }

// ---------------- CSR build ----------------
__global__ void zero_cnt_k() {
    int i = blockIdx.x * blockDim.x + threadIdx.x;
    if (i < NN) g_cnt[i] = 0;
}

__global__ void count_k(const int* __restrict__ ei) {
    int e = blockIdx.x * blockDim.x + threadIdx.x;
    if (e >= ETOT) return;
    int s, d; edge_sd(ei, e, s, d);
    atomicAdd(&g_cnt[d], 1);
}

__global__ void scanA_k() {
    __shared__ int sh[SCAN_B];
    int t = threadIdx.x;
    int i = blockIdx.x * SCAN_B + t;
    int v = (i < NN) ? g_cnt[i] : 0;
    sh[t] = v;
    __syncthreads();
    #pragma unroll
    for (int off = 1; off < SCAN_B; off <<= 1) {
        int tmp = (t >= off) ? sh[t - off] : 0;
        __syncthreads();
        if (t >= off) sh[t] += tmp;
        __syncthreads();
    }
    if (i < NN) g_rowptr[i] = sh[t] - v;          // local exclusive
    if (t == SCAN_B - 1) g_bsum[blockIdx.x] = sh[t];
}

__global__ void scanB_k() {
    __shared__ int sh[64];
    int t = threadIdx.x;
    int v = (t < NBLK) ? g_bsum[t] : 0;
    sh[t] = v;
    __syncthreads();
    #pragma unroll
    for (int off = 1; off < 64; off <<= 1) {
        int tmp = (t >= off) ? sh[t - off] : 0;
        __syncthreads();
        if (t >= off) sh[t] += tmp;
        __syncthreads();
    }
    if (t < NBLK) g_boff[t] = sh[t] - v;          // block exclusive offsets
    if (t == 63) g_rowptr[NN] = sh[63];           // = ETOT
}

__global__ void scanC_k() {
    int i = blockIdx.x * blockDim.x + threadIdx.x;
    if (i >= NN) return;
    int r = g_rowptr[i] + g_boff[i >> 10];
    g_rowptr[i] = r;
    g_cursor[i] = r;
}

__global__ void scatter_k(const int* __restrict__ ei) {
    int e = blockIdx.x * blockDim.x + threadIdx.x;
    if (e >= ETOT) return;
    int s, d; edge_sd(ei, e, s, d);
    int pos = atomicAdd(&g_cursor[d], 1);
    g_srcs[pos] = s;
}

// ---------------- SGEMM core: register-blocked fp32, double-buffered smem ------
// Computes acc[TM][TN] for this thread and stores C. Epilogue logic is supplied
// by the caller via the accumulators (returned through a struct of refs pattern:
// here we inline two variants below instead).
template <int BM, int BN, int BK, int TM, int TN>
struct SgemmCore {
    static constexpr int THREADS = (BM / TM) * (BN / TN);
    static constexpr int A_ITERS = (BM * BK + THREADS * 4 - 1) / (THREADS * 4);
    static constexpr int B_ITERS = (BK * BN + THREADS * 4 - 1) / (THREADS * 4);

    __device__ static void run(const float* __restrict__ A,
                               const float* __restrict__ B,
                               float* __restrict__ C,
                               int M, int K, int Ncol,
                               float (&acc)[TM][TN],
                               int& rowBaseOut, int& tyOut, int& txOut) {
        __shared__ float As[2][BK][BM];
        __shared__ float Bs[2][BK][BN];

        const int tid = threadIdx.x;
        const int tx = tid % (BN / TN);
        const int ty = tid / (BN / TN);
        const int rowBase = blockIdx.x * BM;
        const int colBase = blockIdx.y * BN;
        rowBaseOut = rowBase; tyOut = ty; txOut = tx;

        #pragma unroll
        for (int i = 0; i < TM; i++)
            #pragma unroll
            for (int j = 0; j < TN; j++) acc[i][j] = 0.f;

        float4 ra[A_ITERS], rb[B_ITERS];

        auto fetch = [&](int k0) {
            #pragma unroll
            for (int it = 0; it < A_ITERS; it++) {
                int i = tid * 4 + it * THREADS * 4;
                if (i < BM * BK) {
                    int m = i / BK, kk = i % BK;
                    int gm = rowBase + m;
                    ra[it] = (gm < M)
                        ? *reinterpret_cast<const float4*>(&A[(long)gm * K + k0 + kk])
                        : make_float4(0.f, 0.f, 0.f, 0.f);
                }
            }
            #pragma unroll
            for (int it = 0; it < B_ITERS; it++) {
                int i = tid * 4 + it * THREADS * 4;
                if (i < BK * BN) {
                    int kk = i / BN, nn = i % BN;
                    rb[it] = *reinterpret_cast<const float4*>(&B[(long)(k0 + kk) * Ncol + colBase + nn]);
                }
            }
        };
        auto stash = [&](int buf) {
            #pragma unroll
            for (int it = 0; it < A_ITERS; it++) {
                int i = tid * 4 + it * THREADS * 4;
                if (i < BM * BK) {
                    int m = i / BK, kk = i % BK;
                    As[buf][kk + 0][m] = ra[it].x;
                    As[buf][kk + 1][m] = ra[it].y;
                    As[buf][kk + 2][m] = ra[it].z;
                    As[buf][kk + 3][m] = ra[it].w;
                }
            }
            #pragma unroll
            for (int it = 0; it < B_ITERS; it++) {
                int i = tid * 4 + it * THREADS * 4;
                if (i < BK * BN) {
                    int kk = i / BN, nn = i % BN;
                    *reinterpret_cast<float4*>(&Bs[buf][kk][nn]) = rb[it];
                }
            }
        };

        fetch(0);
        stash(0);
        __syncthreads();

        int cur = 0;
        for (int k0 = 0; k0 < K; k0 += BK) {
            bool has_next = (k0 + BK < K);
            if (has_next) fetch(k0 + BK);

            #pragma unroll
            for (int kk = 0; kk < BK; kk++) {
                float aR[TM], bR[TN];
                #pragma unroll
                for (int i = 0; i < TM; i++) aR[i] = As[cur][kk][ty * TM + i];
                #pragma unroll
                for (int j = 0; j < TN; j++) bR[j] = Bs[cur][kk][tx * TN + j];
                #pragma unroll
                for (int i = 0; i < TM; i++)
                    #pragma unroll
                    for (int j = 0; j < TN; j++)
                        acc[i][j] = fmaf(aR[i], bR[j], acc[i][j]);
            }

            if (has_next) stash(cur ^ 1);
            __syncthreads();
            cur ^= 1;
        }

        #pragma unroll
        for (int i = 0; i < TM; i++) {
            int gm = rowBase + ty * TM + i;
            if (gm >= M) continue;
            #pragma unroll
            for (int j = 0; j < TN; j += 4) {
                float4 v = make_float4(acc[i][j], acc[i][j + 1], acc[i][j + 2], acc[i][j + 3]);
                *reinterpret_cast<float4*>(&C[(long)gm * Ncol + colBase + tx * TN + j]) = v;
            }
        }
    }
};

// GEMM1 + fused per-head logits. Block cols = 128 = heads [4*by, 4*by+4); each
// thread's 8 cols lie in head (4*by + tx/4); reduce over the 4-lane tx subgroup.
__global__ void __launch_bounds__(256) sgemm1_k(const float* __restrict__ x,
                                                const float* __restrict__ W1,
                                                const float* __restrict__ a1s,
                                                const float* __restrict__ a1d) {
    float acc[8][8];
    int rowBase, ty, tx;
    SgemmCore<128, 128, 16, 8, 8>::run(x, W1, g_h1p, NN, FIN, C1, acc, rowBase, ty, tx);

    const int colBase = blockIdx.y * 128;
    const int cbase = colBase + tx * 8;
    float asr[8], adr[8];
    #pragma unroll
    for (int j = 0; j < 8; j++) { asr[j] = a1s[cbase + j]; adr[j] = a1d[cbase + j]; }

    const int head = (cbase >> 5);            // = 4*by + tx/4
    #pragma unroll
    for (int i = 0; i < 8; i++) {
        float s1 = 0.f, s2 = 0.f;
        #pragma unroll
        for (int j = 0; j < 8; j++) {
            s1 = fmaf(acc[i][j], asr[j], s1);
            s2 = fmaf(acc[i][j], adr[j], s2);
        }
        // reduce across the 4 lanes holding this head's 32 channels
        s1 += __shfl_down_sync(FULL, s1, 2); s1 += __shfl_down_sync(FULL, s1, 1);
        s2 += __shfl_down_sync(FULL, s2, 2); s2 += __shfl_down_sync(FULL, s2, 1);
        int gm = rowBase + ty * 8 + i;
        if ((tx & 3) == 0 && gm < NN) {
            g_al1[gm * HEADS + head] = s1;
            g_ar1[gm * HEADS + head] = s2;
        }
    }
}

// GEMM2 + fused single-head logits. BN=64 covers all channels; reduce over the
// 16-lane tx group (shfl_down 8,4,2,1; only tx==0 result valid).
__global__ void __launch_bounds__(256) sgemm2_k(const float* __restrict__ W2,
                                                const float* __restrict__ a2s,
                                                const float* __restrict__ a2d) {
    float acc[8][4];
    int rowBase, ty, tx;
    SgemmCore<128, 64, 16, 8, 4>::run(g_h1, W2, g_h2p, NN, C1, OUTC, acc, rowBase, ty, tx);

    const int cbase = tx * 4;
    float asr[4], adr[4];
    #pragma unroll
    for (int j = 0; j < 4; j++) { asr[j] = a2s[cbase + j]; adr[j] = a2d[cbase + j]; }

    #pragma unroll
    for (int i = 0; i < 8; i++) {
        float s1 = 0.f, s2 = 0.f;
        #pragma unroll
        for (int j = 0; j < 4; j++) {
            s1 = fmaf(acc[i][j], asr[j], s1);
            s2 = fmaf(acc[i][j], adr[j], s2);
        }
        #pragma unroll
        for (int o = 8; o; o >>= 1) {
            s1 += __shfl_down_sync(FULL, s1, o);
            s2 += __shfl_down_sync(FULL, s2, o);
        }
        int gm = rowBase + ty * 8 + i;
        if (tx == 0 && gm < NN) { g_al2[gm] = s1; g_ar2[gm] = s2; }
    }
}

// ---------------- fused GAT aggregation, layer 1 ----------------
// block = dst node, warp w = head w, lane l = channel l
// (src, logit) for the first CHUNKS edge-chunks are register-cached across passes.
__global__ void __launch_bounds__(256) agg1_k(const float* __restrict__ bias) {
    int n = blockIdx.x;
    int w = threadIdx.x >> 5;
    int l = threadIdx.x & 31;
    int beg = g_rowptr[n], end = g_rowptr[n + 1];
    float arn = g_ar1[n * HEADS + w];

    int   sbuf[CHUNKS];
    float vbuf[CHUNKS];

    // pass 1: online softmax, caching (src, v) per chunk
    float m = -1e30f, d = 0.f;
    {
        int c = 0;
        for (int e0 = beg; e0 < end; e0 += 32, c++) {
            int e = e0 + l;
            int s = 0;
            float v = -1e30f;                       // inactive lane -> exp underflows to 0
            if (e < end) {
                s = g_srcs[e];
                v = lrelu(g_al1[s * HEADS + w] + arn);
            }
            if (c < CHUNKS) { sbuf[c] = s; vbuf[c] = v; }
            if (v > m) { d *= __expf(m - v); m = v; }
            d += __expf(v - m);
        }
    }
    warp_softmax_merge(m, d);
    float inv = 1.f / (d + 1e-16f);

    // pass 2: weighted aggregation, chunked shfl-broadcast; reuse cached logits
    float acc = 0.f;
    {
        int c = 0;
        for (int e0 = beg; e0 < end; e0 += 32, c++) {
            int s; float alpha;
            if (c < CHUNKS) {
                s = sbuf[c];
                alpha = __expf(vbuf[c] - m) * inv;  // 0 for inactive lanes
            } else {
                int e = e0 + l;
                s = 0; alpha = 0.f;
                if (e < end) {
                    s = g_srcs[e];
                    alpha = __expf(lrelu(g_al1[s * HEADS + w] + arn) - m) * inv;
                }
            }
            int cnt = min(32, end - e0);
            for (int j = 0; j < cnt; j++) {
                int   sj = __shfl_sync(FULL, s,     j);
                float aj = __shfl_sync(FULL, alpha, j);
                acc = fmaf(g_h1p[sj * C1 + w * HID + l], aj, acc);
            }
        }
    }
    float z = acc + bias[w * HID + l];
    g_h1[n * C1 + w * HID + l] = (z > 0.f) ? z : expm1f(z);  // ELU
}

// ---------------- fused GAT aggregation + log_softmax, layer 2 ----------------
// warp per dst node; lane l handles channels l and l+32
__global__ void __launch_bounds__(256) agg2_k(const float* __restrict__ bias,
                                              float* __restrict__ out) {
    int n = (blockIdx.x * blockDim.x + threadIdx.x) >> 5;
    int l = threadIdx.x & 31;
    if (n >= NN) return;
    int beg = g_rowptr[n], end = g_rowptr[n + 1];
    float arn = g_ar2[n];

    int   sbuf[CHUNKS];
    float vbuf[CHUNKS];

    // pass 1: online softmax with register caching
    float m = -1e30f, d = 0.f;
    {
        int c = 0;
        for (int e0 = beg; e0 < end; e0 += 32, c++) {
            int e = e0 + l;
            int s = 0;
            float v = -1e30f;
            if (e < end) {
                s = g_srcs[e];
                v = lrelu(g_al2[s] + arn);
            }
            if (c < CHUNKS) { sbuf[c] = s; vbuf[c] = v; }
            if (v > m) { d *= __expf(m - v); m = v; }
            d += __expf(v - m);
        }
    }
    warp_softmax_merge(m, d);
    float inv = 1.f / (d + 1e-16f);

    // pass 2: chunked aggregation, reuse cached logits
    float a0 = 0.f, a1 = 0.f;
    {
        int c = 0;
        for (int e0 = beg; e0 < end; e0 += 32, c++) {
            int s; float alpha;
            if (c < CHUNKS) {
                s = sbuf[c];
                alpha = __expf(vbuf[c] - m) * inv;
            } else {
                int e = e0 + l;
                s = 0; alpha = 0.f;
                if (e < end) {
                    s = g_srcs[e];
                    alpha = __expf(lrelu(g_al2[s] + arn) - m) * inv;
                }
            }
            int cnt = min(32, end - e0);
            for (int j = 0; j < cnt; j++) {
                int   sj = __shfl_sync(FULL, s,     j);
                float aj = __shfl_sync(FULL, alpha, j);
                a0 = fmaf(g_h2p[sj * OUTC + l],      aj, a0);
                a1 = fmaf(g_h2p[sj * OUTC + 32 + l], aj, a1);
            }
        }
    }
    float z0 = a0 + bias[l];
    float z1 = a1 + bias[32 + l];

    // warp-wide log_softmax over the 64 channels
    float mx = warp_max(fmaxf(z0, z1));
    float se = warp_sum(__expf(z0 - mx) + __expf(z1 - mx));
    float lse = __logf(se) + mx;
    out[n * OUTC + l]      = z0 - lse;
    out[n * OUTC + 32 + l] = z1 - lse;
}

// ---------------- launcher ----------------
extern "C" void kernel_launch(void* const* d_in, const int* in_sizes, int n_in,
                              void* d_out, int out_size) {
    const float* x   = (const float*)d_in[0];
    const int*   ei  = (const int*)  d_in[1];
    const float* W1  = (const float*)d_in[2];
    const float* a1s = (const float*)d_in[3];
    const float* a1d = (const float*)d_in[4];
    const float* b1  = (const float*)d_in[5];
    const float* W2  = (const float*)d_in[6];
    const float* a2s = (const float*)d_in[7];
    const float* a2d = (const float*)d_in[8];
    const float* b2  = (const float*)d_in[9];
    float* out = (float*)d_out;

    // CSR build
    zero_cnt_k<<<(NN + 255) / 256, 256>>>();
    count_k<<<(ETOT + 255) / 256, 256>>>(ei);
    scanA_k<<<NBLK, SCAN_B>>>();
    scanB_k<<<1, 64>>>();
    scanC_k<<<(NN + 255) / 256, 256>>>();
    scatter_k<<<(ETOT + 255) / 256, 256>>>(ei);

    // layer 1 (logits fused into GEMM epilogue)
    dim3 g1((NN + 127) / 128, C1 / 128);
    sgemm1_k<<<g1, 256>>>(x, W1, a1s, a1d);
    agg1_k<<<NN, 256>>>(b1);

    // layer 2 (logits fused into GEMM epilogue)
    dim3 g2((NN + 127) / 128, OUTC / 64);
    sgemm2_k<<<g2, 256>>>(W2, a2s, a2d);
    agg2_k<<<(NN * 32 + 255) / 256, 256>>>(b2, out);
}